// round 14
// baseline (speedup 1.0000x reference)
#include <cuda_runtime.h>
#include <cstdint>

// DynamicConv2d: B=64, C=8, H=W=256, OUT_C=8, K=3
// v10: v9 fused single-shot-smem kernel, restructured to 2 output rows per
//      thread (block 128, 4 CTAs/SM). Each weight set feeds 96 FMAs; input
//      rows shared across the overlapping ky windows. Ideal fma-frac 80%.

typedef unsigned long long ull;

#define NB   64
#define NC   8
#define NOC  8
#define HW   256

__device__ __forceinline__ ull fma2(ull a, ull b, ull c) {
    ull d;
    asm("fma.rn.f32x2 %0, %1, %2, %3;" : "=l"(d) : "l"(a), "l"(b), "l"(c));
    return d;
}

__device__ __forceinline__ ull pack2(uint32_t lo, uint32_t hi) {
    ull d;
    asm("mov.b64 %0, {%1, %2};" : "=l"(d) : "r"(lo), "r"(hi));
    return d;
}

__device__ __forceinline__ ull dup2(float v) {
    ull d;
    asm("mov.b64 %0, {%1, %1};" : "=l"(d) : "f"(v));
    return d;
}

__device__ __forceinline__ void cp16(uint32_t saddr, const void* g, int srcsz) {
    asm volatile("cp.async.cg.shared.global [%0], [%1], %2, %3;\n"
                 :: "r"(saddr), "l"(g), "n"(16), "r"(srcsz));
}

#define SROWS 18            // 16 output rows + 2 halo
#define RST   76            // row stride in floats (72 data + 4 pad), 16B-aligned
#define BUFSZ (SROWS * RST) // 1368 floats per channel tile
#define NCHUNK 18           // 16B chunks per row: global x in [x0-4, x0+68)

// block: 128 = 16 xt (4 px each -> 64 wide) x 8 ty (2 rows each -> 16 tall)
// grid: (4, 16, 64)
__global__ void __launch_bounds__(128, 4) conv_kernel(const float* __restrict__ x,
                                                      const float* __restrict__ dw,
                                                      const float* __restrict__ Wg,
                                                      const float* __restrict__ bg,
                                                      float* __restrict__ out) {
    // 8 channel tiles + weights: 8*1368 + 576 floats = 45.0 KB (< 48KB static)
    __shared__ alignas(16) float sb[NC * BUFSZ + 576];
    float* ws = sb + NC * BUFSZ;

    const int b  = blockIdx.z;
    const int x0 = blockIdx.x * 64;
    const int y0 = blockIdx.y * 16;
    const int tid = threadIdx.x;
    const int xt = tid & 15;       // 4 px each
    const int ty = tid >> 4;       // 2 rows each (output rows y0+2ty, y0+2ty+1)

    // ---- 1. issue all cp.async tile loads (8 channels) ----
    {
        const float* xb = x + ((size_t)b * NC) * (HW * HW);
        uint32_t sbase = (uint32_t)__cvta_generic_to_shared(sb);
#pragma unroll
        for (int c = 0; c < NC; c++) {
            const float* xp = xb + (size_t)c * (HW * HW);
            uint32_t cb = sbase + (uint32_t)(c * BUFSZ) * 4u;
#pragma unroll
            for (int it = 0; it < 3; it++) {
                int i = tid + it * 128;
                if (i < SROWS * NCHUNK) {
                    int row = i / NCHUNK;
                    int k   = i - row * NCHUNK;
                    int gy  = y0 - 1 + row;
                    int gx0 = x0 - 4 + k * 4;
                    // chunks are fully in-bounds or fully out (x0 % 64 == 0)
                    bool inb = ((unsigned)gy < (unsigned)HW) && ((unsigned)gx0 < (unsigned)HW);
                    const float* src = inb ? (xp + gy * HW + gx0) : xp;
                    cp16(cb + (uint32_t)(row * RST + k * 4) * 4u, src, inb ? 16 : 0);
                }
            }
        }
    }
    asm volatile("cp.async.commit_group;\n");

    // ---- 2. fused weight generation (overlaps the async fill) ----
    // ws[p], p = (ci*9+ky*3+kx)*8 + o
    {
        const float* dwb = dw + b * 64;
#pragma unroll
        for (int it = 0; it < 5; it++) {
            int p = tid + it * 128;
            if (p < 576) {
                int o = p & 7;
                int j = p >> 3;
                float s = __ldg(bg + j);
                const float* dwp = dwb + o * 8;
                const float* wgp = Wg + j * 8;
#pragma unroll
                for (int i = 0; i < 8; i++) s = fmaf(__ldg(dwp + i), __ldg(wgp + i), s);
                ws[p] = s;
            }
        }
    }

    // ---- 3. single wait + sync ----
    asm volatile("cp.async.wait_group 0;\n");
    __syncthreads();

    // acc[r][g][op] : r = output row (2), g = pixel group (4), op = o-pair (4)
    ull acc[2][4][4];
#pragma unroll
    for (int r = 0; r < 2; r++)
#pragma unroll
        for (int g = 0; g < 4; g++)
#pragma unroll
            for (int op = 0; op < 4; op++) acc[r][g][op] = 0ull;

    // ---- 4. zero-barrier mainloop ----
#pragma unroll
    for (int c = 0; c < NC; c++) {
        const float* cbuf = sb + c * BUFSZ;
#pragma unroll
        for (int ky = 0; ky < 3; ky++) {
            // 12 natural weight pairs for (c,ky): [kx*4 + op] via 6 LDS.128
            ull w[12];
            {
                const ulonglong2* wv = (const ulonglong2*)ws + c * 18 + ky * 6;
#pragma unroll
                for (int j = 0; j < 6; j++) {
                    ulonglong2 u = wv[j];
                    w[2 * j]     = u.x;
                    w[2 * j + 1] = u.y;
                }
            }
            // both output rows consume this weight set (input rows 2ty+r+ky)
#pragma unroll
            for (int r = 0; r < 2; r++) {
                const float* rp = cbuf + (2 * ty + r + ky) * RST + 4 * xt;
                float4 m = *(const float4*)(rp + 4);   // px .. px+3
                float2 l = *(const float2*)(rp + 2);   // px-2, px-1
                float2 h = *(const float2*)(rp + 8);   // px+4, px+5
                ull P[6];
                P[0] = dup2(l.y);
                P[1] = dup2(m.x);
                P[2] = dup2(m.y);
                P[3] = dup2(m.z);
                P[4] = dup2(m.w);
                P[5] = dup2(h.x);
#pragma unroll
                for (int kx = 0; kx < 3; kx++) {
#pragma unroll
                    for (int g = 0; g < 4; g++) {
                        ull a = P[g + kx];
                        acc[r][g][0] = fma2(a, w[kx * 4 + 0], acc[r][g][0]);
                        acc[r][g][1] = fma2(a, w[kx * 4 + 1], acc[r][g][1]);
                        acc[r][g][2] = fma2(a, w[kx * 4 + 2], acc[r][g][2]);
                        acc[r][g][3] = fma2(a, w[kx * 4 + 3], acc[r][g][3]);
                    }
                }
            }
        }
    }

    // ---- 5. epilogue: transpose o-pairs -> pixel-quad 16B stores ----
#pragma unroll
    for (int r = 0; r < 2; r++) {
        int gy = y0 + 2 * ty + r;
        size_t base = ((size_t)b * NOC) * (HW * HW) + (size_t)gy * HW + x0 + 4 * xt;
#pragma unroll
        for (int op = 0; op < 4; op++) {
            uint32_t lo[4], hi[4];
#pragma unroll
            for (int g = 0; g < 4; g++) {
                asm("mov.b64 {%0, %1}, %2;" : "=r"(lo[g]), "=r"(hi[g]) : "l"(acc[r][g][op]));
            }
            ulonglong2 v;
            v.x = pack2(lo[0], lo[1]);
            v.y = pack2(lo[2], lo[3]);
            *(ulonglong2*)(out + base + (size_t)(2 * op) * (HW * HW)) = v;
            v.x = pack2(hi[0], hi[1]);
            v.y = pack2(hi[2], hi[3]);
            *(ulonglong2*)(out + base + (size_t)(2 * op + 1) * (HW * HW)) = v;
        }
    }
}

extern "C" void kernel_launch(void* const* d_in, const int* in_sizes, int n_in,
                              void* d_out, int out_size) {
    const float* x  = (const float*)d_in[0];
    const float* dw = (const float*)d_in[1];
    const float* Wg = (const float*)d_in[2];
    const float* bg = (const float*)d_in[3];
    float* out = (float*)d_out;

    dim3 grid(HW / 64, HW / 16, NB);
    conv_kernel<<<grid, 128>>>(x, dw, Wg, bg, out);
}

// round 15
// speedup vs baseline: 1.0595x; 1.0595x over previous
#include <cuda_runtime.h>
#include <cstdint>

// DynamicConv2d: B=64, C=8, H=W=256, OUT_C=8, K=3
// v11: v10 body (2 rows/thread, block 128, 4 CTAs/SM) + split-fill double
//      buffer: channels 0-3 / 4-7 as two cp.async groups; compute on group A
//      overlaps the in-flight fill of group B. 2 barriers total.

typedef unsigned long long ull;

#define NB   64
#define NC   8
#define NOC  8
#define HW   256

__device__ __forceinline__ ull fma2(ull a, ull b, ull c) {
    ull d;
    asm("fma.rn.f32x2 %0, %1, %2, %3;" : "=l"(d) : "l"(a), "l"(b), "l"(c));
    return d;
}

__device__ __forceinline__ ull pack2(uint32_t lo, uint32_t hi) {
    ull d;
    asm("mov.b64 %0, {%1, %2};" : "=l"(d) : "r"(lo), "r"(hi));
    return d;
}

__device__ __forceinline__ ull dup2(float v) {
    ull d;
    asm("mov.b64 %0, {%1, %1};" : "=l"(d) : "f"(v));
    return d;
}

__device__ __forceinline__ void cp16(uint32_t saddr, const void* g, int srcsz) {
    asm volatile("cp.async.cg.shared.global [%0], [%1], %2, %3;\n"
                 :: "r"(saddr), "l"(g), "n"(16), "r"(srcsz));
}

#define SROWS 18            // 16 output rows + 2 halo
#define RST   76            // row stride in floats (72 data + 4 pad), 16B-aligned
#define BUFSZ (SROWS * RST) // 1368 floats per channel tile
#define NCHUNK 18           // 16B chunks per row: global x in [x0-4, x0+68)

// block: 128 = 16 xt (4 px each -> 64 wide) x 8 ty (2 rows each -> 16 tall)
// grid: (4, 16, 64)
__global__ void __launch_bounds__(128, 4) conv_kernel(const float* __restrict__ x,
                                                      const float* __restrict__ dw,
                                                      const float* __restrict__ Wg,
                                                      const float* __restrict__ bg,
                                                      float* __restrict__ out) {
    // 8 channel tiles + weights: 8*1368 + 576 floats = 45.0 KB (< 48KB static)
    __shared__ alignas(16) float sb[NC * BUFSZ + 576];
    float* ws = sb + NC * BUFSZ;

    const int b  = blockIdx.z;
    const int x0 = blockIdx.x * 64;
    const int y0 = blockIdx.y * 16;
    const int tid = threadIdx.x;
    const int xt = tid & 15;       // 4 px each
    const int ty = tid >> 4;       // 2 rows each (output rows y0+2ty, y0+2ty+1)

    const float* xb = x + ((size_t)b * NC) * (HW * HW);
    uint32_t sbase = (uint32_t)__cvta_generic_to_shared(sb);

    auto fill_group = [&](int c_begin) {
#pragma unroll
        for (int cc = 0; cc < 4; cc++) {
            int c = c_begin + cc;
            const float* xp = xb + (size_t)c * (HW * HW);
            uint32_t cbp = sbase + (uint32_t)(c * BUFSZ) * 4u;
#pragma unroll
            for (int it = 0; it < 3; it++) {
                int i = tid + it * 128;
                if (i < SROWS * NCHUNK) {
                    int row = i / NCHUNK;
                    int k   = i - row * NCHUNK;
                    int gy  = y0 - 1 + row;
                    int gx0 = x0 - 4 + k * 4;
                    // chunks are fully in-bounds or fully out (x0 % 64 == 0)
                    bool inb = ((unsigned)gy < (unsigned)HW) && ((unsigned)gx0 < (unsigned)HW);
                    const float* src = inb ? (xp + gy * HW + gx0) : xp;
                    cp16(cbp + (uint32_t)(row * RST + k * 4) * 4u, src, inb ? 16 : 0);
                }
            }
        }
    };

    // ---- 1. two cp.async groups: A = c0-3, B = c4-7 ----
    fill_group(0);
    asm volatile("cp.async.commit_group;\n");
    fill_group(4);
    asm volatile("cp.async.commit_group;\n");

    // ---- 2. fused weight generation (overlaps the async fills) ----
    // ws[p], p = (ci*9+ky*3+kx)*8 + o
    {
        const float* dwb = dw + b * 64;
#pragma unroll
        for (int it = 0; it < 5; it++) {
            int p = tid + it * 128;
            if (p < 576) {
                int o = p & 7;
                int j = p >> 3;
                float s = __ldg(bg + j);
                const float* dwp = dwb + o * 8;
                const float* wgp = Wg + j * 8;
#pragma unroll
                for (int i = 0; i < 8; i++) s = fmaf(__ldg(dwp + i), __ldg(wgp + i), s);
                ws[p] = s;
            }
        }
    }

    // acc[r][g][op] : r = output row (2), g = pixel group (4), op = o-pair (4)
    ull acc[2][4][4];
#pragma unroll
    for (int r = 0; r < 2; r++)
#pragma unroll
        for (int g = 0; g < 4; g++)
#pragma unroll
            for (int op = 0; op < 4; op++) acc[r][g][op] = 0ull;

    // channel-group compute (zero-barrier inside)
    auto compute_group = [&](int c_begin) {
#pragma unroll
        for (int cc = 0; cc < 4; cc++) {
            int c = c_begin + cc;
            const float* cbuf = sb + c * BUFSZ;
#pragma unroll
            for (int ky = 0; ky < 3; ky++) {
                // 12 natural weight pairs for (c,ky): [kx*4 + op] via 6 LDS.128
                ull w[12];
                {
                    const ulonglong2* wv = (const ulonglong2*)ws + c * 18 + ky * 6;
#pragma unroll
                    for (int j = 0; j < 6; j++) {
                        ulonglong2 u = wv[j];
                        w[2 * j]     = u.x;
                        w[2 * j + 1] = u.y;
                    }
                }
#pragma unroll
                for (int r = 0; r < 2; r++) {
                    const float* rp = cbuf + (2 * ty + r + ky) * RST + 4 * xt;
                    float4 m = *(const float4*)(rp + 4);   // px .. px+3
                    float2 l = *(const float2*)(rp + 2);   // px-2, px-1
                    float2 h = *(const float2*)(rp + 8);   // px+4, px+5
                    ull P[6];
                    P[0] = dup2(l.y);
                    P[1] = dup2(m.x);
                    P[2] = dup2(m.y);
                    P[3] = dup2(m.z);
                    P[4] = dup2(m.w);
                    P[5] = dup2(h.x);
#pragma unroll
                    for (int kx = 0; kx < 3; kx++) {
#pragma unroll
                        for (int g = 0; g < 4; g++) {
                            ull a = P[g + kx];
                            acc[r][g][0] = fma2(a, w[kx * 4 + 0], acc[r][g][0]);
                            acc[r][g][1] = fma2(a, w[kx * 4 + 1], acc[r][g][1]);
                            acc[r][g][2] = fma2(a, w[kx * 4 + 2], acc[r][g][2]);
                            acc[r][g][3] = fma2(a, w[kx * 4 + 3], acc[r][g][3]);
                        }
                    }
                }
            }
        }
    };

    // ---- 3. group A ready -> compute A while B streams in ----
    asm volatile("cp.async.wait_group 1;\n");
    __syncthreads();
    compute_group(0);

    // ---- 4. group B ready -> compute B ----
    asm volatile("cp.async.wait_group 0;\n");
    __syncthreads();
    compute_group(4);

    // ---- 5. epilogue: transpose o-pairs -> pixel-quad 16B stores ----
#pragma unroll
    for (int r = 0; r < 2; r++) {
        int gy = y0 + 2 * ty + r;
        size_t base = ((size_t)b * NOC) * (HW * HW) + (size_t)gy * HW + x0 + 4 * xt;
#pragma unroll
        for (int op = 0; op < 4; op++) {
            uint32_t lo[4], hi[4];
#pragma unroll
            for (int g = 0; g < 4; g++) {
                asm("mov.b64 {%0, %1}, %2;" : "=r"(lo[g]), "=r"(hi[g]) : "l"(acc[r][g][op]));
            }
            ulonglong2 v;
            v.x = pack2(lo[0], lo[1]);
            v.y = pack2(lo[2], lo[3]);
            *(ulonglong2*)(out + base + (size_t)(2 * op) * (HW * HW)) = v;
            v.x = pack2(hi[0], hi[1]);
            v.y = pack2(hi[2], hi[3]);
            *(ulonglong2*)(out + base + (size_t)(2 * op + 1) * (HW * HW)) = v;
        }
    }
}

extern "C" void kernel_launch(void* const* d_in, const int* in_sizes, int n_in,
                              void* d_out, int out_size) {
    const float* x  = (const float*)d_in[0];
    const float* dw = (const float*)d_in[1];
    const float* Wg = (const float*)d_in[2];
    const float* bg = (const float*)d_in[3];
    float* out = (float*)d_out;

    dim3 grid(HW / 64, HW / 16, NB);
    conv_kernel<<<grid, 128>>>(x, dw, Wg, bg, out);
}